// round 1
// baseline (speedup 1.0000x reference)
#include <cuda_runtime.h>
#include <math.h>

// Problem constants (match reference)
#define BTOK 4096   // B tokens
#define DDIM 2048   // D
#define HDIM 4096   // H
#define NEXP 8      // E experts
#define TOPK 2

// ---------------------------------------------------------------------------
// Device-global scratch (no allocation allowed): per-expert dispatch lists.
// Each token appears in exactly TOPK=2 expert lists; capacity B per expert.
// ---------------------------------------------------------------------------
__device__ int   d_cnt[NEXP];
__device__ int   d_tok[NEXP * BTOK];
__device__ float d_wt [NEXP * BTOK];

// ---------------------------------------------------------------------------
// Kernel 0: zero output region [0, B*H) and counters.
// grid: (B*H/4)/256 blocks, 256 threads, float4 stores.
// ---------------------------------------------------------------------------
__global__ void zero_kernel(float4* __restrict__ out)
{
    size_t i = (size_t)blockIdx.x * blockDim.x + threadIdx.x;
    out[i] = make_float4(0.f, 0.f, 0.f, 0.f);
    if (blockIdx.x == 0 && threadIdx.x < NEXP) d_cnt[threadIdx.x] = 0;
}

// ---------------------------------------------------------------------------
// Kernel 1: gate. One block per token, 256 threads.
//  logits[e] = x[b] . gW[e][:D] + emb[label[b]] . gW[e][D:] + gb[e]
//  top-2 (descending, ties -> lower index, matching lax.top_k),
//  softmax over the 2 winners, dispatch into per-expert lists,
//  write topk_idx tail of output (as float).
// ---------------------------------------------------------------------------
__global__ __launch_bounds__(256) void gate_kernel(
    const float* __restrict__ x,
    const int*   __restrict__ labels,
    const float* __restrict__ emb,
    const float* __restrict__ gw,     // [E, 2D]
    const float* __restrict__ gb,     // [E]
    float*       __restrict__ out_tail)  // out + B*H, or nullptr
{
    const int b   = blockIdx.x;
    const int tid = threadIdx.x;

    const float4* xr = (const float4*)(x   + (size_t)b * DDIM);
    const float4* er = (const float4*)(emb + (size_t)labels[b] * DDIM);

    float acc[NEXP];
#pragma unroll
    for (int e = 0; e < NEXP; e++) acc[e] = 0.f;

    // D/4 = 512 float4 chunks, 2 iterations per thread
    for (int j = tid; j < DDIM / 4; j += 256) {
        float4 xv = xr[j];
        float4 ev = er[j];
#pragma unroll
        for (int e = 0; e < NEXP; e++) {
            const float4* g  = (const float4*)(gw + (size_t)e * 2 * DDIM);
            float4 g1 = g[j];
            float4 g2 = g[DDIM / 4 + j];
            acc[e] += xv.x * g1.x + xv.y * g1.y + xv.z * g1.z + xv.w * g1.w
                    + ev.x * g2.x + ev.y * g2.y + ev.z * g2.z + ev.w * g2.w;
        }
    }

    // warp reduce each expert accumulator
#pragma unroll
    for (int e = 0; e < NEXP; e++)
#pragma unroll
        for (int o = 16; o > 0; o >>= 1)
            acc[e] += __shfl_xor_sync(0xffffffffu, acc[e], o);

    __shared__ float red[8][NEXP];
    const int w = tid >> 5, l = tid & 31;
    if (l == 0) {
#pragma unroll
        for (int e = 0; e < NEXP; e++) red[w][e] = acc[e];
    }
    __syncthreads();

    if (tid == 0) {
        float lg[NEXP];
#pragma unroll
        for (int e = 0; e < NEXP; e++) {
            float s = gb[e];
#pragma unroll
            for (int ww = 0; ww < 8; ww++) s += red[ww][e];
            lg[e] = s;
        }
        // top-2 with lowest-index tie-break (strict >)
        int i0 = 0;
#pragma unroll
        for (int e = 1; e < NEXP; e++) if (lg[e] > lg[i0]) i0 = e;
        int i1 = -1;
#pragma unroll
        for (int e = 0; e < NEXP; e++) {
            if (e == i0) continue;
            if (i1 < 0 || lg[e] > lg[i1]) i1 = e;
        }
        // softmax over [lg[i0], lg[i1]] with lg[i0] >= lg[i1]
        float p0 = 1.f / (1.f + expf(lg[i1] - lg[i0]));
        float p1 = 1.f - p0;

        int s0 = atomicAdd(&d_cnt[i0], 1);
        d_tok[i0 * BTOK + s0] = b;
        d_wt [i0 * BTOK + s0] = p0;
        int s1 = atomicAdd(&d_cnt[i1], 1);
        d_tok[i1 * BTOK + s1] = b;
        d_wt [i1 * BTOK + s1] = p1;

        if (out_tail) {
            out_tail[2 * b + 0] = (float)i0;
            out_tail[2 * b + 1] = (float)i1;
        }
    }
}

// ---------------------------------------------------------------------------
// Kernel 2: grouped expert GEMM + weighted scatter-add combine.
// grid: (H/BN, B/BM, E). Blocks beyond the expert's token count exit early.
// C[i,h] = sum_d x[tok[i],d] * W[e][h,d]; out[tok] += w * (C + bias)
// 128x128x8 tiles, 8x8 micro-tile per thread, register-prefetched gmem loads.
// ---------------------------------------------------------------------------
#define BM 128
#define BN 128
#define BK 8

__global__ __launch_bounds__(256) void expert_kernel(
    const float* __restrict__ x,
    const float* __restrict__ eW,   // [E, H, D]
    const float* __restrict__ eb,   // [E, H]
    float*       __restrict__ out)  // [B, H]
{
    const int e  = blockIdx.z;
    const int ne = d_cnt[e];
    const int m0 = blockIdx.y * BM;
    if (m0 >= ne) return;
    const int n0 = blockIdx.x * BN;

    __shared__ float As[BK][BM];
    __shared__ float Bs[BK][BN];

    const int tid = threadIdx.x;
    const int lr  = tid >> 1;          // 0..127: tile row loaded by this thread
    const int lc  = (tid & 1) << 2;    // 0 or 4: float4 column offset in BK

    const int arow = m0 + lr;
    const int tokA = d_tok[e * BTOK + (arow < ne ? arow : m0)];
    const float* ap = x  + (size_t)tokA * DDIM + lc;
    const float* bp = eW + ((size_t)e * HDIM + n0 + lr) * DDIM + lc;

    const int tm = (tid >> 4) << 3;    // 0..120, step 8
    const int tn = (tid & 15) << 3;    // 0..120, step 8

    float acc[8][8];
#pragma unroll
    for (int i = 0; i < 8; i++)
#pragma unroll
        for (int j = 0; j < 8; j++) acc[i][j] = 0.f;

    float4 av = *(const float4*)(ap);
    float4 bv = *(const float4*)(bp);

    for (int k0 = 0; k0 < DDIM; k0 += BK) {
        __syncthreads();
        As[lc + 0][lr] = av.x; As[lc + 1][lr] = av.y;
        As[lc + 2][lr] = av.z; As[lc + 3][lr] = av.w;
        Bs[lc + 0][lr] = bv.x; Bs[lc + 1][lr] = bv.y;
        Bs[lc + 2][lr] = bv.z; Bs[lc + 3][lr] = bv.w;
        __syncthreads();

        // prefetch next stage while computing (LDG overlaps FFMA)
        if (k0 + BK < DDIM) {
            av = *(const float4*)(ap + k0 + BK);
            bv = *(const float4*)(bp + k0 + BK);
        }

#pragma unroll
        for (int k = 0; k < BK; k++) {
            float4 a0 = *(const float4*)&As[k][tm];
            float4 a1 = *(const float4*)&As[k][tm + 4];
            float4 b0 = *(const float4*)&Bs[k][tn];
            float4 b1 = *(const float4*)&Bs[k][tn + 4];
            float a[8]  = {a0.x, a0.y, a0.z, a0.w, a1.x, a1.y, a1.z, a1.w};
            float bb[8] = {b0.x, b0.y, b0.z, b0.w, b1.x, b1.y, b1.z, b1.w};
#pragma unroll
            for (int i = 0; i < 8; i++)
#pragma unroll
                for (int j = 0; j < 8; j++)
                    acc[i][j] += a[i] * bb[j];
        }
    }

    // epilogue: weighted scatter-add with bias
    float bias[8];
#pragma unroll
    for (int j = 0; j < 8; j++)
        bias[j] = eb[(size_t)e * HDIM + n0 + tn + j];

#pragma unroll
    for (int i = 0; i < 8; i++) {
        const int row = m0 + tm + i;
        if (row < ne) {
            const int   tok = d_tok[e * BTOK + row];
            const float w   = d_wt [e * BTOK + row];
            float* op = out + (size_t)tok * HDIM + n0 + tn;
#pragma unroll
            for (int j = 0; j < 8; j++)
                atomicAdd(op + j, w * (acc[i][j] + bias[j]));
        }
    }
}

// ---------------------------------------------------------------------------
// Launch
// ---------------------------------------------------------------------------
extern "C" void kernel_launch(void* const* d_in, const int* in_sizes, int n_in,
                              void* d_out, int out_size)
{
    const float* x      = (const float*)d_in[0];  // [B, D]
    const int*   labels = (const int*)  d_in[1];  // [B]
    const float* emb    = (const float*)d_in[2];  // [NDIFF, D]
    const float* gw     = (const float*)d_in[3];  // [E, 2D]
    const float* gb     = (const float*)d_in[4];  // [E]
    const float* eW     = (const float*)d_in[5];  // [E, H, D]
    const float* eb     = (const float*)d_in[6];  // [E, H]
    float* out = (float*)d_out;

    const size_t main_elems = (size_t)BTOK * HDIM;
    float* tail = ((size_t)out_size >= main_elems + 2 * BTOK)
                      ? out + main_elems : nullptr;

    zero_kernel<<<(BTOK * (HDIM / 4)) / 256, 256>>>((float4*)out);
    gate_kernel<<<BTOK, 256>>>(x, labels, emb, gw, gb, tail);
    expert_kernel<<<dim3(HDIM / BN, BTOK / BM, NEXP), 256>>>(x, eW, eb, out);
}

// round 3
// speedup vs baseline: 2.9000x; 2.9000x over previous
#include <cuda_runtime.h>
#include <math.h>
#include <stdint.h>

#define BTOK 4096
#define DDIM 2048
#define HDIM 4096
#define NEXP 8

// ---------------------------------------------------------------------------
// Device-global scratch (no allocation allowed)
// ---------------------------------------------------------------------------
__device__ int   d_cnt[NEXP];
__device__ int   d_tok[NEXP * BTOK];
__device__ float d_wt [NEXP * BTOK];
__device__ float d_Xr [(size_t)BTOK * DDIM];          // tf32-rounded activations (32MB)
__device__ float d_Wr [(size_t)NEXP * HDIM * DDIM];   // tf32-rounded weights (256MB)

// ---------------------------------------------------------------------------
// helpers
// ---------------------------------------------------------------------------
__device__ __forceinline__ uint32_t smem_u32(const void* p) {
    uint32_t a;
    asm("{ .reg .u64 t; cvta.to.shared.u64 t, %1; cvt.u32.u64 %0, t; }" : "=r"(a) : "l"(p));
    return a;
}
__device__ __forceinline__ float rna_tf32(float x) {
    uint32_t u;
    asm("cvt.rna.tf32.f32 %0, %1;" : "=r"(u) : "f"(x));
    return __uint_as_float(u);
}
#define CPASYNC16(dst, src) \
    asm volatile("cp.async.cg.shared.global [%0], [%1], 16;" :: "r"(dst), "l"(src))
#define CPCOMMIT() asm volatile("cp.async.commit_group;" ::: "memory")
#define CPWAIT(n)  asm volatile("cp.async.wait_group %0;" :: "n"(n) : "memory")

// mma.sync m16n8k8 tf32: D = A*B + C (in place on acc)
__device__ __forceinline__ void mma_tf32(float* c, const uint32_t* a, const uint32_t* b) {
    asm volatile(
        "mma.sync.aligned.m16n8k8.row.col.f32.tf32.tf32.f32 "
        "{%0,%1,%2,%3}, {%4,%5,%6,%7}, {%8,%9}, {%0,%1,%2,%3};"
        : "+f"(c[0]), "+f"(c[1]), "+f"(c[2]), "+f"(c[3])
        : "r"(a[0]), "r"(a[1]), "r"(a[2]), "r"(a[3]), "r"(b[0]), "r"(b[1]));
}

// ---------------------------------------------------------------------------
// Kernel 0: zero output [0, B*H) + counters
// ---------------------------------------------------------------------------
__global__ void zero_kernel(float4* __restrict__ out)
{
    size_t i = (size_t)blockIdx.x * blockDim.x + threadIdx.x;
    out[i] = make_float4(0.f, 0.f, 0.f, 0.f);
    if (blockIdx.x == 0 && threadIdx.x < NEXP) d_cnt[threadIdx.x] = 0;
}

// ---------------------------------------------------------------------------
// Kernel 1a/1b: round W and x to tf32 (rna)
// ---------------------------------------------------------------------------
__global__ void wround_kernel(const float4* __restrict__ W)
{
    size_t i = (size_t)blockIdx.x * blockDim.x + threadIdx.x;
    float4 v = W[i];
    v.x = rna_tf32(v.x); v.y = rna_tf32(v.y);
    v.z = rna_tf32(v.z); v.w = rna_tf32(v.w);
    ((float4*)d_Wr)[i] = v;
}
__global__ void xround_kernel(const float4* __restrict__ X)
{
    size_t i = (size_t)blockIdx.x * blockDim.x + threadIdx.x;
    float4 v = X[i];
    v.x = rna_tf32(v.x); v.y = rna_tf32(v.y);
    v.z = rna_tf32(v.z); v.w = rna_tf32(v.w);
    ((float4*)d_Xr)[i] = v;
}

// ---------------------------------------------------------------------------
// Kernel 2: gate (unchanged — validated in R1)
// ---------------------------------------------------------------------------
__global__ __launch_bounds__(256) void gate_kernel(
    const float* __restrict__ x, const int* __restrict__ labels,
    const float* __restrict__ emb, const float* __restrict__ gw,
    const float* __restrict__ gb, float* __restrict__ out_tail)
{
    const int b   = blockIdx.x;
    const int tid = threadIdx.x;
    const float4* xr = (const float4*)(x   + (size_t)b * DDIM);
    const float4* er = (const float4*)(emb + (size_t)labels[b] * DDIM);

    float acc[NEXP];
#pragma unroll
    for (int e = 0; e < NEXP; e++) acc[e] = 0.f;

    for (int j = tid; j < DDIM / 4; j += 256) {
        float4 xv = xr[j];
        float4 ev = er[j];
#pragma unroll
        for (int e = 0; e < NEXP; e++) {
            const float4* g  = (const float4*)(gw + (size_t)e * 2 * DDIM);
            float4 g1 = g[j];
            float4 g2 = g[DDIM / 4 + j];
            acc[e] += xv.x * g1.x + xv.y * g1.y + xv.z * g1.z + xv.w * g1.w
                    + ev.x * g2.x + ev.y * g2.y + ev.z * g2.z + ev.w * g2.w;
        }
    }
#pragma unroll
    for (int e = 0; e < NEXP; e++)
#pragma unroll
        for (int o = 16; o > 0; o >>= 1)
            acc[e] += __shfl_xor_sync(0xffffffffu, acc[e], o);

    __shared__ float red[8][NEXP];
    const int w = tid >> 5, l = tid & 31;
    if (l == 0) {
#pragma unroll
        for (int e = 0; e < NEXP; e++) red[w][e] = acc[e];
    }
    __syncthreads();

    if (tid == 0) {
        float lg[NEXP];
#pragma unroll
        for (int e = 0; e < NEXP; e++) {
            float s = gb[e];
#pragma unroll
            for (int ww = 0; ww < 8; ww++) s += red[ww][e];
            lg[e] = s;
        }
        int i0 = 0;
#pragma unroll
        for (int e = 1; e < NEXP; e++) if (lg[e] > lg[i0]) i0 = e;
        int i1 = -1;
#pragma unroll
        for (int e = 0; e < NEXP; e++) {
            if (e == i0) continue;
            if (i1 < 0 || lg[e] > lg[i1]) i1 = e;
        }
        float p0 = 1.f / (1.f + expf(lg[i1] - lg[i0]));
        float p1 = 1.f - p0;

        int s0 = atomicAdd(&d_cnt[i0], 1);
        d_tok[i0 * BTOK + s0] = b;
        d_wt [i0 * BTOK + s0] = p0;
        int s1 = atomicAdd(&d_cnt[i1], 1);
        d_tok[i1 * BTOK + s1] = b;
        d_wt [i1 * BTOK + s1] = p1;

        if (out_tail) {
            out_tail[2 * b + 0] = (float)i0;
            out_tail[2 * b + 1] = (float)i1;
        }
    }
}

// ---------------------------------------------------------------------------
// Kernel 3: grouped tf32 mma.sync GEMM + weighted combine.
// Tile 128x128x32, 4-stage cp.async, 8 warps of 64x32 warp-tiles.
// grid: (HDIM/128, BTOK/128, NEXP)
// ---------------------------------------------------------------------------
#define BM 128
#define BN 128
#define BK 32
#define NCH (DDIM / BK)          // 64
#define NST 4
#define ASTRIDE 36               // floats; 144B rows (16B aligned), conflict-free
#define A_FLOATS (BM * ASTRIDE)  // 4608
#define STAGE_BYTES (2 * A_FLOATS * 4)          // 36864
#define META_OFF (NST * STAGE_BYTES)            // 147456
#define SMEM_TOTAL (META_OFF + 1536)

__global__ __launch_bounds__(256, 1) void moe_gemm(
    const float* __restrict__ eb,   // [E, H]
    float*       __restrict__ out)  // [B, H]
{
    const int e  = blockIdx.z;
    const int ne = d_cnt[e];
    const int m0 = blockIdx.y * BM;
    if (m0 >= ne) return;
    const int n0 = blockIdx.x * BN;

    extern __shared__ char smem[];
    int*   stok_s  = (int*)  (smem + META_OFF);
    float* swt_s   = (float*)(smem + META_OFF + 512);
    float* sbias_s = (float*)(smem + META_OFF + 1024);

    const int tid = threadIdx.x;
    const int wid = tid >> 5, lid = tid & 31;
    const int g = lid >> 2, t = lid & 3;
    const int wm = wid >> 2, wn = wid & 3;      // 2 x 4 warp grid

    if (tid < BM) {
        int m = m0 + tid;
        bool v = (m < ne);
        stok_s[tid] = v ? d_tok[e * BTOK + m] : d_tok[e * BTOK];
        swt_s [tid] = v ? d_wt [e * BTOK + m] : 0.f;
        sbias_s[tid] = eb[(size_t)e * HDIM + n0 + tid];
    }
    __syncthreads();

    const uint32_t sb = smem_u32(smem);
    const float* Bbase = d_Wr + ((size_t)e * HDIM + n0) * DDIM;

    auto load_stage = [&](int c) {
        const uint32_t stg = sb + (uint32_t)(c & (NST - 1)) * STAGE_BYTES;
        const int k0 = c * BK;
        // A: 128 rows x 8 x 16B, indirect via token list
#pragma unroll
        for (int i = 0; i < 4; i++) {
            int ch = tid + 256 * i;
            int row = ch >> 3, k16 = ch & 7;
            const float* src = d_Xr + (size_t)stok_s[row] * DDIM + k0 + k16 * 4;
            CPASYNC16(stg + (uint32_t)(row * 144 + k16 * 16), src);
        }
        // B: 128 rows x 8 x 16B
        const uint32_t stgB = stg + (uint32_t)(A_FLOATS * 4);
#pragma unroll
        for (int i = 0; i < 4; i++) {
            int ch = tid + 256 * i;
            int row = ch >> 3, k16 = ch & 7;
            const float* src = Bbase + (size_t)row * DDIM + k0 + k16 * 4;
            CPASYNC16(stgB + (uint32_t)(row * 144 + k16 * 16), src);
        }
    };

    float acc[4][4][4];
#pragma unroll
    for (int mf = 0; mf < 4; mf++)
#pragma unroll
        for (int nf = 0; nf < 4; nf++)
#pragma unroll
            for (int k = 0; k < 4; k++) acc[mf][nf][k] = 0.f;

#pragma unroll
    for (int p = 0; p < NST - 1; p++) { load_stage(p); CPCOMMIT(); }

    for (int kt = 0; kt < NCH; kt++) {
        CPWAIT(NST - 2);
        __syncthreads();
        if (kt + NST - 1 < NCH) load_stage(kt + NST - 1);
        CPCOMMIT();

        const float* As = (const float*)(smem + (kt & (NST - 1)) * STAGE_BYTES);
        const float* Bs = As + A_FLOATS;

#pragma unroll
        for (int ks = 0; ks < 4; ks++) {
            const int k0 = ks * 8;
            uint32_t a[4][4], b[4][2];
#pragma unroll
            for (int mf = 0; mf < 4; mf++) {
                const float* ap = As + (wm * 64 + mf * 16 + g) * ASTRIDE + k0 + t;
                a[mf][0] = __float_as_uint(ap[0]);
                a[mf][1] = __float_as_uint(ap[8 * ASTRIDE]);
                a[mf][2] = __float_as_uint(ap[4]);
                a[mf][3] = __float_as_uint(ap[8 * ASTRIDE + 4]);
            }
#pragma unroll
            for (int nf = 0; nf < 4; nf++) {
                const float* bp = Bs + (wn * 32 + nf * 8 + g) * ASTRIDE + k0 + t;
                b[nf][0] = __float_as_uint(bp[0]);
                b[nf][1] = __float_as_uint(bp[4]);
            }
#pragma unroll
            for (int mf = 0; mf < 4; mf++)
#pragma unroll
                for (int nf = 0; nf < 4; nf++)
                    mma_tf32(acc[mf][nf], a[mf], b[nf]);
        }
    }

    // epilogue: wt * (acc + bias) scattered via vector RED
#pragma unroll
    for (int mf = 0; mf < 4; mf++) {
        const int lr0 = wm * 64 + mf * 16 + g;
        const int lr1 = lr0 + 8;
        const bool v0 = (m0 + lr0) < ne;
        const bool v1 = (m0 + lr1) < ne;
        const float w0 = swt_s[lr0], w1 = swt_s[lr1];
        float* op0 = out + (size_t)stok_s[lr0] * HDIM + n0;
        float* op1 = out + (size_t)stok_s[lr1] * HDIM + n0;
#pragma unroll
        for (int nf = 0; nf < 4; nf++) {
            const int col = wn * 32 + nf * 8 + t * 2;
            const float b0 = sbias_s[col], b1 = sbias_s[col + 1];
            if (v0) {
                float2 v = make_float2(w0 * (acc[mf][nf][0] + b0),
                                       w0 * (acc[mf][nf][1] + b1));
                atomicAdd((float2*)(op0 + col), v);
            }
            if (v1) {
                float2 v = make_float2(w1 * (acc[mf][nf][2] + b0),
                                       w1 * (acc[mf][nf][3] + b1));
                atomicAdd((float2*)(op1 + col), v);
            }
        }
    }
}

// ---------------------------------------------------------------------------
// Launch
// ---------------------------------------------------------------------------
extern "C" void kernel_launch(void* const* d_in, const int* in_sizes, int n_in,
                              void* d_out, int out_size)
{
    const float* x      = (const float*)d_in[0];
    const int*   labels = (const int*)  d_in[1];
    const float* emb    = (const float*)d_in[2];
    const float* gw     = (const float*)d_in[3];
    const float* gb     = (const float*)d_in[4];
    const float* eW     = (const float*)d_in[5];
    const float* ebias  = (const float*)d_in[6];
    float* out = (float*)d_out;

    const size_t main_elems = (size_t)BTOK * HDIM;
    float* tail = ((size_t)out_size >= main_elems + 2 * BTOK)
                      ? out + main_elems : nullptr;

    static int attr_done = 0;
    if (!attr_done) {
        cudaFuncSetAttribute(moe_gemm, cudaFuncAttributeMaxDynamicSharedMemorySize,
                             SMEM_TOTAL);
        attr_done = 1;
    }

    zero_kernel  <<<(BTOK * (HDIM / 4)) / 256, 256>>>((float4*)out);
    xround_kernel<<<((size_t)BTOK * (DDIM / 4)) / 256, 256>>>((const float4*)x);
    wround_kernel<<<((size_t)NEXP * HDIM * (DDIM / 4)) / 256, 256>>>((const float4*)eW);
    gate_kernel  <<<BTOK, 256>>>(x, labels, emb, gw, gb, tail);
    moe_gemm     <<<dim3(HDIM / BN, BTOK / BM, NEXP), 256, SMEM_TOTAL>>>(ebias, out);
}

// round 4
// speedup vs baseline: 5.3293x; 1.8377x over previous
#include <cuda_runtime.h>
#include <cuda_fp16.h>
#include <math.h>
#include <stdint.h>

#define BTOK 4096
#define DDIM 2048
#define HDIM 4096
#define NEXP 8

// ---------------------------------------------------------------------------
// Device-global scratch (no allocation allowed)
// ---------------------------------------------------------------------------
__device__ int    d_cnt[NEXP];
__device__ int    d_tok[NEXP * BTOK];
__device__ float  d_wt [NEXP * BTOK];
__device__ __half d_Xh [(size_t)BTOK * DDIM];          // fp16 activations (16MB)
__device__ __half d_Wh [(size_t)NEXP * HDIM * DDIM];   // fp16 weights (128MB)

// ---------------------------------------------------------------------------
// helpers
// ---------------------------------------------------------------------------
__device__ __forceinline__ uint32_t smem_u32(const void* p) {
    uint32_t a;
    asm("{ .reg .u64 t; cvta.to.shared.u64 t, %1; cvt.u32.u64 %0, t; }" : "=r"(a) : "l"(p));
    return a;
}
#define CPASYNC16(dst, src) \
    asm volatile("cp.async.cg.shared.global [%0], [%1], 16;" :: "r"(dst), "l"(src))
#define CPCOMMIT() asm volatile("cp.async.commit_group;" ::: "memory")
#define CPWAIT(n)  asm volatile("cp.async.wait_group %0;" :: "n"(n) : "memory")

__device__ __forceinline__ void ldsm_x4(uint32_t& r0, uint32_t& r1,
                                        uint32_t& r2, uint32_t& r3, uint32_t addr) {
    asm volatile("ldmatrix.sync.aligned.m8n8.x4.shared.b16 {%0,%1,%2,%3}, [%4];"
                 : "=r"(r0), "=r"(r1), "=r"(r2), "=r"(r3) : "r"(addr));
}

// mma.sync m16n8k16 f16 -> f32
__device__ __forceinline__ void mma_f16(float* c, const uint32_t* a, const uint32_t* b) {
    asm volatile(
        "mma.sync.aligned.m16n8k16.row.col.f32.f16.f16.f32 "
        "{%0,%1,%2,%3}, {%4,%5,%6,%7}, {%8,%9}, {%0,%1,%2,%3};"
        : "+f"(c[0]), "+f"(c[1]), "+f"(c[2]), "+f"(c[3])
        : "r"(a[0]), "r"(a[1]), "r"(a[2]), "r"(a[3]), "r"(b[0]), "r"(b[1]));
}

// ---------------------------------------------------------------------------
// Kernel 0: zero output [0, B*H) + counters
// ---------------------------------------------------------------------------
__global__ void zero_kernel(float4* __restrict__ out)
{
    size_t i = (size_t)blockIdx.x * blockDim.x + threadIdx.x;
    out[i] = make_float4(0.f, 0.f, 0.f, 0.f);
    if (blockIdx.x == 0 && threadIdx.x < NEXP) d_cnt[threadIdx.x] = 0;
}

// ---------------------------------------------------------------------------
// Kernel 1a/1b: convert W and x to fp16 (RN)
// ---------------------------------------------------------------------------
__global__ void wconv_kernel(const float4* __restrict__ W)
{
    size_t i = (size_t)blockIdx.x * blockDim.x + threadIdx.x;
    float4 v = W[i];
    __half2 h0 = __floats2half2_rn(v.x, v.y);
    __half2 h1 = __floats2half2_rn(v.z, v.w);
    uint2 u = make_uint2(*(uint32_t*)&h0, *(uint32_t*)&h1);
    ((uint2*)d_Wh)[i] = u;
}
__global__ void xconv_kernel(const float4* __restrict__ X)
{
    size_t i = (size_t)blockIdx.x * blockDim.x + threadIdx.x;
    float4 v = X[i];
    __half2 h0 = __floats2half2_rn(v.x, v.y);
    __half2 h1 = __floats2half2_rn(v.z, v.w);
    uint2 u = make_uint2(*(uint32_t*)&h0, *(uint32_t*)&h1);
    ((uint2*)d_Xh)[i] = u;
}

// ---------------------------------------------------------------------------
// Kernel 2: gate (unchanged — validated)
// ---------------------------------------------------------------------------
__global__ __launch_bounds__(256) void gate_kernel(
    const float* __restrict__ x, const int* __restrict__ labels,
    const float* __restrict__ emb, const float* __restrict__ gw,
    const float* __restrict__ gb, float* __restrict__ out_tail)
{
    const int b   = blockIdx.x;
    const int tid = threadIdx.x;
    const float4* xr = (const float4*)(x   + (size_t)b * DDIM);
    const float4* er = (const float4*)(emb + (size_t)labels[b] * DDIM);

    float acc[NEXP];
#pragma unroll
    for (int e = 0; e < NEXP; e++) acc[e] = 0.f;

    for (int j = tid; j < DDIM / 4; j += 256) {
        float4 xv = xr[j];
        float4 ev = er[j];
#pragma unroll
        for (int e = 0; e < NEXP; e++) {
            const float4* g  = (const float4*)(gw + (size_t)e * 2 * DDIM);
            float4 g1 = g[j];
            float4 g2 = g[DDIM / 4 + j];
            acc[e] += xv.x * g1.x + xv.y * g1.y + xv.z * g1.z + xv.w * g1.w
                    + ev.x * g2.x + ev.y * g2.y + ev.z * g2.z + ev.w * g2.w;
        }
    }
#pragma unroll
    for (int e = 0; e < NEXP; e++)
#pragma unroll
        for (int o = 16; o > 0; o >>= 1)
            acc[e] += __shfl_xor_sync(0xffffffffu, acc[e], o);

    __shared__ float red[8][NEXP];
    const int w = tid >> 5, l = tid & 31;
    if (l == 0) {
#pragma unroll
        for (int e = 0; e < NEXP; e++) red[w][e] = acc[e];
    }
    __syncthreads();

    if (tid == 0) {
        float lg[NEXP];
#pragma unroll
        for (int e = 0; e < NEXP; e++) {
            float s = gb[e];
#pragma unroll
            for (int ww = 0; ww < 8; ww++) s += red[ww][e];
            lg[e] = s;
        }
        int i0 = 0;
#pragma unroll
        for (int e = 1; e < NEXP; e++) if (lg[e] > lg[i0]) i0 = e;
        int i1 = -1;
#pragma unroll
        for (int e = 0; e < NEXP; e++) {
            if (e == i0) continue;
            if (i1 < 0 || lg[e] > lg[i1]) i1 = e;
        }
        float p0 = 1.f / (1.f + expf(lg[i1] - lg[i0]));
        float p1 = 1.f - p0;

        int s0 = atomicAdd(&d_cnt[i0], 1);
        d_tok[i0 * BTOK + s0] = b;
        d_wt [i0 * BTOK + s0] = p0;
        int s1 = atomicAdd(&d_cnt[i1], 1);
        d_tok[i1 * BTOK + s1] = b;
        d_wt [i1 * BTOK + s1] = p1;

        if (out_tail) {
            out_tail[2 * b + 0] = (float)i0;
            out_tail[2 * b + 1] = (float)i1;
        }
    }
}

// ---------------------------------------------------------------------------
// Kernel 3: grouped fp16 mma.sync GEMM + weighted combine.
// Tile 128x128x64 (halves). 4-stage cp.async, Swizzle<3,4,3>, ldmatrix frags.
// grid: (HDIM/128, BTOK/128, NEXP)
// ---------------------------------------------------------------------------
#define BM 128
#define BN 128
#define BK 64                      // halves; row = 128B
#define NCH (DDIM / BK)            // 32
#define NST 4
#define A_BYTES (BM * 128)         // 16384
#define STAGE_BYTES (2 * A_BYTES)  // 32768
#define META_OFF (NST * STAGE_BYTES)
#define SMEM_TOTAL (META_OFF + 1536)

__global__ __launch_bounds__(256, 1) void moe_gemm(
    const float* __restrict__ eb,   // [E, H]
    float*       __restrict__ out)  // [B, H]
{
    const int e  = blockIdx.z;
    const int ne = d_cnt[e];
    const int m0 = blockIdx.y * BM;
    if (m0 >= ne) return;
    const int n0 = blockIdx.x * BN;

    extern __shared__ char smem[];
    int*   stok_s  = (int*)  (smem + META_OFF);
    float* swt_s   = (float*)(smem + META_OFF + 512);
    float* sbias_s = (float*)(smem + META_OFF + 1024);

    const int tid = threadIdx.x;
    const int wid = tid >> 5, lid = tid & 31;
    const int g = lid >> 2, t = lid & 3;
    const int wm = wid >> 2, wn = wid & 3;    // 2 x 4 warp grid, tile 64x32

    if (tid < BM) {
        int m = m0 + tid;
        bool v = (m < ne);
        stok_s[tid] = v ? d_tok[e * BTOK + m] : d_tok[e * BTOK];
        swt_s [tid] = v ? d_wt [e * BTOK + m] : 0.f;
        sbias_s[tid] = eb[(size_t)e * HDIM + n0 + tid];
    }
    __syncthreads();

    const uint32_t sb = smem_u32(smem);
    const __half* Bbase = d_Wh + ((size_t)e * HDIM + n0) * DDIM;

    // per-thread cp.async indices
    const int ldrow = tid >> 3;          // 0..31 (+32*i)
    const int ldcc  = tid & 7;           // 16B chunk in row

    auto load_stage = [&](int c) {
        const uint32_t stg = sb + (uint32_t)(c & (NST - 1)) * STAGE_BYTES;
        const int k0 = c * BK;
#pragma unroll
        for (int i = 0; i < 4; i++) {
            int row = ldrow + 32 * i;
            const __half* src = d_Xh + (size_t)stok_s[row] * DDIM + k0 + ldcc * 8;
            CPASYNC16(stg + (uint32_t)(row * 128 + ((ldcc ^ (row & 7)) * 16)), src);
        }
        const uint32_t stgB = stg + A_BYTES;
#pragma unroll
        for (int i = 0; i < 4; i++) {
            int row = ldrow + 32 * i;
            const __half* src = Bbase + (size_t)row * DDIM + k0 + ldcc * 8;
            CPASYNC16(stgB + (uint32_t)(row * 128 + ((ldcc ^ (row & 7)) * 16)), src);
        }
    };

    // ldmatrix per-thread row/chunk decomposition
    const int rowA_in = lid & 15;               // row within m16 frag
    const int kA      = lid >> 4;               // 0/1: k-half chunk
    const int rowB_in = (lid & 7) + ((lid >> 4) & 1) * 8;  // row within n16 pair
    const int kB      = (lid >> 3) & 1;

    float acc[4][4][4];
#pragma unroll
    for (int mf = 0; mf < 4; mf++)
#pragma unroll
        for (int nf = 0; nf < 4; nf++)
#pragma unroll
            for (int k = 0; k < 4; k++) acc[mf][nf][k] = 0.f;

#pragma unroll
    for (int p = 0; p < NST - 1; p++) { load_stage(p); CPCOMMIT(); }

    for (int kt = 0; kt < NCH; kt++) {
        CPWAIT(NST - 2);
        __syncthreads();
        if (kt + NST - 1 < NCH) load_stage(kt + NST - 1);
        CPCOMMIT();

        const uint32_t As = sb + (uint32_t)(kt & (NST - 1)) * STAGE_BYTES;
        const uint32_t Bs = As + A_BYTES;

#pragma unroll
        for (int ks = 0; ks < 4; ks++) {
            uint32_t a[4][4], b[4][2];
#pragma unroll
            for (int mf = 0; mf < 4; mf++) {
                const int row = wm * 64 + mf * 16 + rowA_in;
                const int cc  = 2 * ks + kA;
                ldsm_x4(a[mf][0], a[mf][1], a[mf][2], a[mf][3],
                        As + (uint32_t)(row * 128 + ((cc ^ (row & 7)) * 16)));
            }
#pragma unroll
            for (int nf2 = 0; nf2 < 2; nf2++) {
                const int row = wn * 32 + nf2 * 16 + rowB_in;
                const int cc  = 2 * ks + kB;
                ldsm_x4(b[2 * nf2][0], b[2 * nf2][1],
                        b[2 * nf2 + 1][0], b[2 * nf2 + 1][1],
                        Bs + (uint32_t)(row * 128 + ((cc ^ (row & 7)) * 16)));
            }
#pragma unroll
            for (int mf = 0; mf < 4; mf++)
#pragma unroll
                for (int nf = 0; nf < 4; nf++)
                    mma_f16(acc[mf][nf], a[mf], b[nf]);
        }
    }

    // epilogue: wt * (acc + bias) scattered via vector RED
#pragma unroll
    for (int mf = 0; mf < 4; mf++) {
        const int lr0 = wm * 64 + mf * 16 + g;
        const int lr1 = lr0 + 8;
        const bool v0 = (m0 + lr0) < ne;
        const bool v1 = (m0 + lr1) < ne;
        const float w0 = swt_s[lr0], w1 = swt_s[lr1];
        float* op0 = out + (size_t)stok_s[lr0] * HDIM + n0;
        float* op1 = out + (size_t)stok_s[lr1] * HDIM + n0;
#pragma unroll
        for (int nf = 0; nf < 4; nf++) {
            const int col = wn * 32 + nf * 8 + t * 2;
            const float b0 = sbias_s[col], b1 = sbias_s[col + 1];
            if (v0) {
                float2 v = make_float2(w0 * (acc[mf][nf][0] + b0),
                                       w0 * (acc[mf][nf][1] + b1));
                atomicAdd((float2*)(op0 + col), v);
            }
            if (v1) {
                float2 v = make_float2(w1 * (acc[mf][nf][2] + b0),
                                       w1 * (acc[mf][nf][3] + b1));
                atomicAdd((float2*)(op1 + col), v);
            }
        }
    }
}

// ---------------------------------------------------------------------------
// Launch
// ---------------------------------------------------------------------------
extern "C" void kernel_launch(void* const* d_in, const int* in_sizes, int n_in,
                              void* d_out, int out_size)
{
    const float* x      = (const float*)d_in[0];
    const int*   labels = (const int*)  d_in[1];
    const float* emb    = (const float*)d_in[2];
    const float* gw     = (const float*)d_in[3];
    const float* gb     = (const float*)d_in[4];
    const float* eW     = (const float*)d_in[5];
    const float* ebias  = (const float*)d_in[6];
    float* out = (float*)d_out;

    const size_t main_elems = (size_t)BTOK * HDIM;
    float* tail = ((size_t)out_size >= main_elems + 2 * BTOK)
                      ? out + main_elems : nullptr;

    static int attr_done = 0;
    if (!attr_done) {
        cudaFuncSetAttribute(moe_gemm, cudaFuncAttributeMaxDynamicSharedMemorySize,
                             SMEM_TOTAL);
        attr_done = 1;
    }

    zero_kernel <<<(BTOK * (HDIM / 4)) / 256, 256>>>((float4*)out);
    xconv_kernel<<<((size_t)BTOK * (DDIM / 4)) / 256, 256>>>((const float4*)x);
    wconv_kernel<<<((size_t)NEXP * HDIM * (DDIM / 4)) / 256, 256>>>((const float4*)eW);
    gate_kernel <<<BTOK, 256>>>(x, labels, emb, gw, gb, tail);
    moe_gemm    <<<dim3(HDIM / BN, BTOK / BM, NEXP), 256, SMEM_TOTAL>>>(ebias, out);
}

// round 5
// speedup vs baseline: 7.2075x; 1.3524x over previous
#include <cuda_runtime.h>
#include <cuda_fp16.h>
#include <math.h>
#include <stdint.h>

#define BTOK 4096
#define DDIM 2048
#define HDIM 4096
#define NEXP 8

// ---------------------------------------------------------------------------
// Device-global scratch (no allocation allowed)
// ---------------------------------------------------------------------------
__device__ int    d_cnt[NEXP];
__device__ int    d_tok[NEXP * BTOK];
__device__ float  d_wt [NEXP * BTOK];
__device__ __half d_Xh [(size_t)BTOK * DDIM];          // fp16 activations (16MB)
__device__ __half d_Wh [(size_t)NEXP * HDIM * DDIM];   // fp16 weights (128MB)

// ---------------------------------------------------------------------------
// helpers
// ---------------------------------------------------------------------------
__device__ __forceinline__ uint32_t smem_u32(const void* p) {
    uint32_t a;
    asm("{ .reg .u64 t; cvta.to.shared.u64 t, %1; cvt.u32.u64 %0, t; }" : "=r"(a) : "l"(p));
    return a;
}
#define CPASYNC16(dst, src) \
    asm volatile("cp.async.cg.shared.global [%0], [%1], 16;" :: "r"(dst), "l"(src))
#define CPCOMMIT() asm volatile("cp.async.commit_group;" ::: "memory")
#define CPWAIT(n)  asm volatile("cp.async.wait_group %0;" :: "n"(n) : "memory")

__device__ __forceinline__ void ldsm_x4(uint32_t& r0, uint32_t& r1,
                                        uint32_t& r2, uint32_t& r3, uint32_t addr) {
    asm volatile("ldmatrix.sync.aligned.m8n8.x4.shared.b16 {%0,%1,%2,%3}, [%4];"
                 : "=r"(r0), "=r"(r1), "=r"(r2), "=r"(r3) : "r"(addr));
}

__device__ __forceinline__ void mma_f16(float* c, const uint32_t* a, const uint32_t* b) {
    asm volatile(
        "mma.sync.aligned.m16n8k16.row.col.f32.f16.f16.f32 "
        "{%0,%1,%2,%3}, {%4,%5,%6,%7}, {%8,%9}, {%0,%1,%2,%3};"
        : "+f"(c[0]), "+f"(c[1]), "+f"(c[2]), "+f"(c[3])
        : "r"(a[0]), "r"(a[1]), "r"(a[2]), "r"(a[3]), "r"(b[0]), "r"(b[1]));
}

// ---------------------------------------------------------------------------
// Kernel 0: init counters (must precede the fused prep kernel's gate blocks)
// ---------------------------------------------------------------------------
__global__ void init_kernel()
{
    if (threadIdx.x < NEXP) d_cnt[threadIdx.x] = 0;
}

// ---------------------------------------------------------------------------
// Kernel 1: fused prep — role split by blockIdx.x
//   [0, GATE_B)                : gate, one token per block
//   [GATE_B, +ZERO_B)          : zero output main region
//   [.., +XC_B)                : x -> fp16
//   [.., +WC_B)                : W -> fp16
// ---------------------------------------------------------------------------
#define GATE_B 4096
#define ZERO_B 1024
#define XC_B   512
#define WC_B   4096
#define PREP_B (GATE_B + ZERO_B + XC_B + WC_B)

__global__ __launch_bounds__(256) void prep_kernel(
    const float* __restrict__ x, const int* __restrict__ labels,
    const float* __restrict__ emb, const float* __restrict__ gw,
    const float* __restrict__ gb, const float* __restrict__ eW,
    float* __restrict__ out, float* __restrict__ out_tail)
{
    const int bid = blockIdx.x;
    const int tid = threadIdx.x;

    if (bid >= GATE_B) {
        int r = bid - GATE_B;
        if (r < ZERO_B) {
            // zero out[0, B*H): 4M float4 over 1024 blocks -> 16 iters
            float4* o4 = (float4*)out;
            const size_t total = (size_t)BTOK * HDIM / 4;
            for (size_t i = (size_t)r * 256 + tid; i < total; i += (size_t)ZERO_B * 256)
                o4[i] = make_float4(0.f, 0.f, 0.f, 0.f);
            return;
        }
        r -= ZERO_B;
        if (r < XC_B) {
            // x -> fp16: 2M float4 over 512 blocks -> 16 iters
            const float4* X4 = (const float4*)x;
            const size_t total = (size_t)BTOK * DDIM / 4;
            for (size_t i = (size_t)r * 256 + tid; i < total; i += (size_t)XC_B * 256) {
                float4 v = X4[i];
                __half2 h0 = __floats2half2_rn(v.x, v.y);
                __half2 h1 = __floats2half2_rn(v.z, v.w);
                ((uint2*)d_Xh)[i] = make_uint2(*(uint32_t*)&h0, *(uint32_t*)&h1);
            }
            return;
        }
        r -= XC_B;
        {
            // W -> fp16: 16M float4 over 4096 blocks -> 16 iters
            const float4* W4 = (const float4*)eW;
            const size_t total = (size_t)NEXP * HDIM * DDIM / 4;
            for (size_t i = (size_t)r * 256 + tid; i < total; i += (size_t)WC_B * 256) {
                float4 v = W4[i];
                __half2 h0 = __floats2half2_rn(v.x, v.y);
                __half2 h1 = __floats2half2_rn(v.z, v.w);
                ((uint2*)d_Wh)[i] = make_uint2(*(uint32_t*)&h0, *(uint32_t*)&h1);
            }
            return;
        }
    }

    // ---- gate role: token b = bid ----
    const int b = bid;
    const float4* xr = (const float4*)(x   + (size_t)b * DDIM);
    const float4* er = (const float4*)(emb + (size_t)labels[b] * DDIM);

    float acc[NEXP];
#pragma unroll
    for (int e = 0; e < NEXP; e++) acc[e] = 0.f;

    for (int j = tid; j < DDIM / 4; j += 256) {
        float4 xv = xr[j];
        float4 ev = er[j];
#pragma unroll
        for (int e = 0; e < NEXP; e++) {
            const float4* g  = (const float4*)(gw + (size_t)e * 2 * DDIM);
            float4 g1 = g[j];
            float4 g2 = g[DDIM / 4 + j];
            acc[e] += xv.x * g1.x + xv.y * g1.y + xv.z * g1.z + xv.w * g1.w
                    + ev.x * g2.x + ev.y * g2.y + ev.z * g2.z + ev.w * g2.w;
        }
    }
#pragma unroll
    for (int e = 0; e < NEXP; e++)
#pragma unroll
        for (int o = 16; o > 0; o >>= 1)
            acc[e] += __shfl_xor_sync(0xffffffffu, acc[e], o);

    __shared__ float red[8][NEXP];
    const int w = tid >> 5, l = tid & 31;
    if (l == 0) {
#pragma unroll
        for (int e = 0; e < NEXP; e++) red[w][e] = acc[e];
    }
    __syncthreads();

    if (tid == 0) {
        float lg[NEXP];
#pragma unroll
        for (int e = 0; e < NEXP; e++) {
            float s = gb[e];
#pragma unroll
            for (int ww = 0; ww < 8; ww++) s += red[ww][e];
            lg[e] = s;
        }
        int i0 = 0;
#pragma unroll
        for (int e = 1; e < NEXP; e++) if (lg[e] > lg[i0]) i0 = e;
        int i1 = -1;
#pragma unroll
        for (int e = 0; e < NEXP; e++) {
            if (e == i0) continue;
            if (i1 < 0 || lg[e] > lg[i1]) i1 = e;
        }
        float p0 = 1.f / (1.f + expf(lg[i1] - lg[i0]));
        float p1 = 1.f - p0;

        int s0 = atomicAdd(&d_cnt[i0], 1);
        d_tok[i0 * BTOK + s0] = b;
        d_wt [i0 * BTOK + s0] = p0;
        int s1 = atomicAdd(&d_cnt[i1], 1);
        d_tok[i1 * BTOK + s1] = b;
        d_wt [i1 * BTOK + s1] = p1;

        if (out_tail) {
            out_tail[2 * b + 0] = (float)i0;
            out_tail[2 * b + 1] = (float)i1;
        }
    }
}

// ---------------------------------------------------------------------------
// Kernel 2: grouped fp16 mma.sync GEMM + weighted combine.
// Tile 128x128x64 (halves). 3-stage cp.async, 2 CTAs/SM, ldmatrix frags.
// grid: (HDIM/128, BTOK/128, NEXP)
// ---------------------------------------------------------------------------
#define BM 128
#define BN 128
#define BK 64                      // halves; row = 128B
#define NCH (DDIM / BK)            // 32
#define NST 3
#define A_BYTES (BM * 128)         // 16384
#define STAGE_BYTES (2 * A_BYTES)  // 32768
#define META_OFF (NST * STAGE_BYTES)      // 98304
#define SMEM_TOTAL (META_OFF + 1536)

__global__ __launch_bounds__(256, 2) void moe_gemm(
    const float* __restrict__ eb,   // [E, H]
    float*       __restrict__ out)  // [B, H]
{
    const int e  = blockIdx.z;
    const int ne = d_cnt[e];
    const int m0 = blockIdx.y * BM;
    if (m0 >= ne) return;
    const int n0 = blockIdx.x * BN;

    extern __shared__ char smem[];
    int*   stok_s  = (int*)  (smem + META_OFF);
    float* swt_s   = (float*)(smem + META_OFF + 512);
    float* sbias_s = (float*)(smem + META_OFF + 1024);

    const int tid = threadIdx.x;
    const int wid = tid >> 5, lid = tid & 31;
    const int g = lid >> 2, t = lid & 3;
    const int wm = wid >> 2, wn = wid & 3;    // 2 x 4 warp grid, tile 64x32

    if (tid < BM) {
        int m = m0 + tid;
        bool v = (m < ne);
        stok_s[tid] = v ? d_tok[e * BTOK + m] : d_tok[e * BTOK];
        swt_s [tid] = v ? d_wt [e * BTOK + m] : 0.f;
        sbias_s[tid] = eb[(size_t)e * HDIM + n0 + tid];
    }
    __syncthreads();

    const uint32_t sb = smem_u32(smem);
    const __half* Bbase = d_Wh + ((size_t)e * HDIM + n0) * DDIM;

    const int ldrow = tid >> 3;          // 0..31 (+32*i)
    const int ldcc  = tid & 7;           // 16B chunk in row

    auto load_stage = [&](int c) {
        const uint32_t stg = sb + (uint32_t)(c % NST) * STAGE_BYTES;
        const int k0 = c * BK;
#pragma unroll
        for (int i = 0; i < 4; i++) {
            int row = ldrow + 32 * i;
            const __half* src = d_Xh + (size_t)stok_s[row] * DDIM + k0 + ldcc * 8;
            CPASYNC16(stg + (uint32_t)(row * 128 + ((ldcc ^ (row & 7)) * 16)), src);
        }
        const uint32_t stgB = stg + A_BYTES;
#pragma unroll
        for (int i = 0; i < 4; i++) {
            int row = ldrow + 32 * i;
            const __half* src = Bbase + (size_t)row * DDIM + k0 + ldcc * 8;
            CPASYNC16(stgB + (uint32_t)(row * 128 + ((ldcc ^ (row & 7)) * 16)), src);
        }
    };

    const int rowA_in = lid & 15;
    const int kA      = lid >> 4;
    const int rowB_in = (lid & 7) + ((lid >> 4) & 1) * 8;
    const int kB      = (lid >> 3) & 1;

    float acc[4][4][4];
#pragma unroll
    for (int mf = 0; mf < 4; mf++)
#pragma unroll
        for (int nf = 0; nf < 4; nf++)
#pragma unroll
            for (int k = 0; k < 4; k++) acc[mf][nf][k] = 0.f;

#pragma unroll
    for (int p = 0; p < NST - 1; p++) { load_stage(p); CPCOMMIT(); }

    for (int kt = 0; kt < NCH; kt++) {
        CPWAIT(NST - 2);
        __syncthreads();
        if (kt + NST - 1 < NCH) load_stage(kt + NST - 1);
        CPCOMMIT();

        const uint32_t As = sb + (uint32_t)(kt % NST) * STAGE_BYTES;
        const uint32_t Bs = As + A_BYTES;

#pragma unroll
        for (int ks = 0; ks < 4; ks++) {
            uint32_t a[4][4], b[4][2];
#pragma unroll
            for (int mf = 0; mf < 4; mf++) {
                const int row = wm * 64 + mf * 16 + rowA_in;
                const int cc  = 2 * ks + kA;
                ldsm_x4(a[mf][0], a[mf][1], a[mf][2], a[mf][3],
                        As + (uint32_t)(row * 128 + ((cc ^ (row & 7)) * 16)));
            }
#pragma unroll
            for (int nf2 = 0; nf2 < 2; nf2++) {
                const int row = wn * 32 + nf2 * 16 + rowB_in;
                const int cc  = 2 * ks + kB;
                ldsm_x4(b[2 * nf2][0], b[2 * nf2][1],
                        b[2 * nf2 + 1][0], b[2 * nf2 + 1][1],
                        Bs + (uint32_t)(row * 128 + ((cc ^ (row & 7)) * 16)));
            }
#pragma unroll
            for (int mf = 0; mf < 4; mf++)
#pragma unroll
                for (int nf = 0; nf < 4; nf++)
                    mma_f16(acc[mf][nf], a[mf], b[nf]);
        }
    }

    // epilogue: wt * (acc + bias) scattered via vector RED
#pragma unroll
    for (int mf = 0; mf < 4; mf++) {
        const int lr0 = wm * 64 + mf * 16 + g;
        const int lr1 = lr0 + 8;
        const bool v0 = (m0 + lr0) < ne;
        const bool v1 = (m0 + lr1) < ne;
        const float w0 = swt_s[lr0], w1 = swt_s[lr1];
        float* op0 = out + (size_t)stok_s[lr0] * HDIM + n0;
        float* op1 = out + (size_t)stok_s[lr1] * HDIM + n0;
#pragma unroll
        for (int nf = 0; nf < 4; nf++) {
            const int col = wn * 32 + nf * 8 + t * 2;
            const float b0 = sbias_s[col], b1 = sbias_s[col + 1];
            if (v0) {
                float2 v = make_float2(w0 * (acc[mf][nf][0] + b0),
                                       w0 * (acc[mf][nf][1] + b1));
                atomicAdd((float2*)(op0 + col), v);
            }
            if (v1) {
                float2 v = make_float2(w1 * (acc[mf][nf][2] + b0),
                                       w1 * (acc[mf][nf][3] + b1));
                atomicAdd((float2*)(op1 + col), v);
            }
        }
    }
}

// ---------------------------------------------------------------------------
// Launch
// ---------------------------------------------------------------------------
extern "C" void kernel_launch(void* const* d_in, const int* in_sizes, int n_in,
                              void* d_out, int out_size)
{
    const float* x      = (const float*)d_in[0];
    const int*   labels = (const int*)  d_in[1];
    const float* emb    = (const float*)d_in[2];
    const float* gw     = (const float*)d_in[3];
    const float* gb     = (const float*)d_in[4];
    const float* eW     = (const float*)d_in[5];
    const float* ebias  = (const float*)d_in[6];
    float* out = (float*)d_out;

    const size_t main_elems = (size_t)BTOK * HDIM;
    float* tail = ((size_t)out_size >= main_elems + 2 * BTOK)
                      ? out + main_elems : nullptr;

    static int attr_done = 0;
    if (!attr_done) {
        cudaFuncSetAttribute(moe_gemm, cudaFuncAttributeMaxDynamicSharedMemorySize,
                             SMEM_TOTAL);
        attr_done = 1;
    }

    init_kernel<<<1, 32>>>();
    prep_kernel<<<PREP_B, 256>>>(x, labels, emb, gw, gb, eW, out, tail);
    moe_gemm   <<<dim3(HDIM / BN, BTOK / BM, NEXP), 256, SMEM_TOTAL>>>(ebias, out);
}